// round 2
// baseline (speedup 1.0000x reference)
#include <cuda_runtime.h>
#include <cstdint>

// Problem constants (fixed by reference setup_inputs).
constexpr int N_MOLS      = 2000;
constexpr int N_PER_MOL   = 64;
constexpr int PAIRS_PER_M = N_PER_MOL * (N_PER_MOL - 1);   // 4032
constexpr float CUTOFF    = 5.0f;

// Output layout (flatten of reference tuple, all cast to float32):
//   [0,    P)  : i_idx
//   [P,   2P)  : j_idx
//   [2P,  3P)  : d_ij
//   [3P,  6P)  : r_ij (row-major [P,3])
// with P = N_MOLS * PAIRS_PER_M = 8,064,000.

__global__ __launch_bounds__(256)
void neighborlist_kernel(const float* __restrict__ pos, float* __restrict__ out)
{
    __shared__ float sx[N_PER_MOL];
    __shared__ float sy[N_PER_MOL];
    __shared__ float sz[N_PER_MOL];

    const int m = blockIdx.x;
    const int t = threadIdx.x;

    // Stage this molecule's 64 positions into shared.
    if (t < N_PER_MOL) {
        const float* p = pos + (size_t)(m * N_PER_MOL + t) * 3;
        sx[t] = p[0];
        sy[t] = p[1];
        sz[t] = p[2];
    }
    __syncthreads();

    const size_t P    = (size_t)N_MOLS * PAIRS_PER_M;
    float* __restrict__ out_i = out;
    float* __restrict__ out_j = out + P;
    float* __restrict__ out_d = out + 2 * P;
    float* __restrict__ out_r = out + 3 * P;

    const size_t base = (size_t)m * PAIRS_PER_M;
    const int atom_base = m * N_PER_MOL;

    for (int p = t; p < PAIRS_PER_M; p += 256) {
        // Decode ordered pair (i, j) with i != j; ordering matches the
        // reference template: for i in [0,64), j skips j==i.
        const int i  = p / 63;                 // const-div -> mul/shift
        const int jr = p - i * 63;
        const int j  = jr + (jr >= i ? 1 : 0);

        const float dx = sx[j] - sx[i];
        const float dy = sy[j] - sy[i];
        const float dz = sz[j] - sz[i];
        const float d  = sqrtf(fmaf(dx, dx, fmaf(dy, dy, dz * dz)));

        const bool in_cut = (d <= CUTOFF);
        const float dd = in_cut ? d  : 0.0f;
        const float rx = in_cut ? dx : 0.0f;
        const float ry = in_cut ? dy : 0.0f;
        const float rz = in_cut ? dz : 0.0f;

        const size_t g = base + p;
        out_i[g] = (float)(atom_base + i);
        out_j[g] = (float)(atom_base + j);
        out_d[g] = dd;

        float* __restrict__ r = out_r + 3 * g;
        r[0] = rx;
        r[1] = ry;
        r[2] = rz;
    }
}

extern "C" void kernel_launch(void* const* d_in, const int* in_sizes, int n_in,
                              void* d_out, int out_size)
{
    const float* pos = (const float*)d_in[0];
    float* out = (float*)d_out;
    neighborlist_kernel<<<N_MOLS, 256>>>(pos, out);
}